// round 15
// baseline (speedup 1.0000x reference)
#include <cuda_runtime.h>
#include <cuda_bf16.h>
#include <cuda_fp16.h>
#include <cstdint>

// Problem constants
#define BSZ   32
#define SSZ   1024
#define DSZ   768
#define HSZ   128
#define RSZ   48
#define APP   (SSZ + 1)        // 1025
#define NTOK  (BSZ * SSZ)      // 32768
#define MHEAD (BSZ * APP)      // 32800

// Scratch (device globals)
__device__ __half g_headH[(size_t)MHEAD * HSZ];           // fp16 head
__device__ __half g_tailH[(size_t)NTOK * HSZ];            // fp16 tail
__device__ __half g_W16[(size_t)2 * HSZ * DSZ];           // W^T [branch][n][k] fp16
// Fragment-ordered fp16 B image per r: uint4 units: r*2048 + ks*256 + g*32 + lane
__device__ uint4 g_Bfrag[(size_t)RSZ * 2048];

// ---------------------------------------------------------------------------
// PTX helpers (target-suffix-free)
// ---------------------------------------------------------------------------
__device__ __forceinline__ uint32_t smem_u32(const void* p) {
    uint32_t a;
    asm("{ .reg .u64 t; cvta.to.shared.u64 t, %1; cvt.u32.u64 %0, t; }" : "=r"(a) : "l"(p));
    return a;
}

#define CP16(dst, src) \
    asm volatile("cp.async.cg.shared.global [%0], [%1], 16;" :: "r"(dst), "l"(src) : "memory")
#define CP_COMMIT() asm volatile("cp.async.commit_group;" ::: "memory")
#define CP_WAIT0()  asm volatile("cp.async.wait_group 0;" ::: "memory")
#define CP_WAIT1()  asm volatile("cp.async.wait_group 1;" ::: "memory")

#define LDMX4(r, addr) \
    asm volatile("ldmatrix.sync.aligned.m8n8.x4.shared.b16 {%0,%1,%2,%3}, [%4];" \
        : "=r"((r)[0]), "=r"((r)[1]), "=r"((r)[2]), "=r"((r)[3]) : "r"(addr))

// fp16 MMA
#define MMA_FP(c, a, b0, b1) \
    asm volatile("mma.sync.aligned.m16n8k16.row.col.f32.f16.f16.f32 " \
        "{%0,%1,%2,%3}, {%4,%5,%6,%7}, {%8,%9}, {%0,%1,%2,%3};" \
        : "+f"((c)[0]), "+f"((c)[1]), "+f"((c)[2]), "+f"((c)[3]) \
        : "r"((a)[0]), "r"((a)[1]), "r"((a)[2]), "r"((a)[3]), "r"(b0), "r"(b1))

__device__ __forceinline__ uint32_t pack_fp16(__half a, __half b) {
    return (uint32_t)__half_as_ushort(a) | ((uint32_t)__half_as_ushort(b) << 16);
}

// ---------------------------------------------------------------------------
// Kernel 0: fused prep. grid (48, 5).  (proven in R14)
// ---------------------------------------------------------------------------
__global__ __launch_bounds__(256) void prep_all(const float* __restrict__ Kmat,
                                                const float* __restrict__ Wh,
                                                const float* __restrict__ Wt)
{
    __shared__ float stage[32 * 129];
    const int tid = threadIdx.x;

    if (blockIdx.y < 4) {
        const int r = blockIdx.x;
        const int q = blockIdx.y;
#pragma unroll
        for (int j = 0; j < 16; j++) {
            int idx = tid + j * 256;
            int h = idx >> 7, n = idx & 127;
            stage[h * 129 + n] = Kmat[(size_t)(q * 32 + h) * (HSZ * RSZ) + r * HSZ + n];
        }
        __syncthreads();

        uint32_t* outH = (uint32_t*)(g_Bfrag + (size_t)r * 2048);
#pragma unroll
        for (int j = 0; j < 8; j++) {
            int v = q * 2048 + tid + j * 256;
            int ks   = v >> 10;
            int rem  = v & 1023;
            int g    = rem >> 7;
            int rem2 = rem & 127;
            int lane = rem2 >> 2;
            int hw2  = rem2 & 3;
            int pair = hw2 >> 1, reg = hw2 & 1;
            int n  = (2 * g + pair) * 8 + (lane >> 2);
            int h0 = ks * 16 + reg * 8 + (lane & 3) * 2 - q * 32;
            float f0 = stage[h0 * 129 + n];
            float f1 = stage[(h0 + 1) * 129 + n];
            outH[v] = pack_fp16(__float2half_rn(f0), __float2half_rn(f1));
        }
    } else {
        if (blockIdx.x >= 48) return;
        const int kb = blockIdx.x % 24;
        const int br = blockIdx.x / 24;
        const float* W = br ? Wt : Wh;
#pragma unroll
        for (int j = 0; j < 16; j++) {
            int idx = tid + j * 256;
            int k = idx >> 7;
            int n = idx & 127;
            stage[k * 129 + n] = W[(size_t)(kb * 32 + k) * HSZ + n];
        }
        __syncthreads();
#pragma unroll
        for (int j = 0; j < 16; j++) {
            int idx = tid + j * 256;
            int n = idx >> 5;
            int k = idx & 31;
            g_W16[(size_t)br * HSZ * DSZ + (size_t)n * DSZ + kb * 32 + k] =
                __float2half_rn(stage[k * 129 + n]);
        }
    }
}

// ---------------------------------------------------------------------------
// Kernel 1: dual FF GEMM, fp16 1-pass (proven in R10-R14).
// ---------------------------------------------------------------------------
#define FFROW 80
#define FF_AT (128 * FFROW)                        // 10240
#define FF_BB FF_AT
#define FF_BS FF_AT
#define FF_SMEM (FF_BB + 2 * FF_BS)                // 30720

__global__ __launch_bounds__(256) void ff_mma(
    const float* __restrict__ x,
    const float* __restrict__ root,
    const float* __restrict__ bh, const float* __restrict__ bt)
{
    extern __shared__ char sm[];
    const uint32_t sb = smem_u32(sm);

    const int branch = blockIdx.y;
    const int M      = (branch == 0) ? MHEAD : NTOK;
    const int m0     = blockIdx.x * 128;
    if (m0 >= M) return;

    const float* bias = (branch == 0) ? bh : bt;
    const __half* WB  = g_W16 + (size_t)branch * HSZ * DSZ;

    const int tid  = threadIdx.x;
    const int lane = tid & 31;
    const int warp = tid >> 5;
    const int wm   = warp >> 2;
    const int wn   = warp & 3;

    const float* arow[4];
    bool rowok[4];
    int rown[4], colf[4];
#pragma unroll
    for (int i = 0; i < 4; i++) {
        int c   = tid + i * 256;
        int row = c >> 3;
        int c4  = c & 7;
        rown[i] = row; colf[i] = c4;
        int g = m0 + row;
        const float* p = nullptr;
        bool ok = (g < M);
        if (ok) {
            if (branch == 0) {
                int b  = g / APP;
                int ii = g - b * APP;
                p = (ii == 0) ? root : (x + (size_t)(b * SSZ + (ii - 1)) * DSZ);
            } else {
                p = x + (size_t)g * DSZ;
            }
        }
        arow[i] = p; rowok[i] = ok;
    }

    auto load_B = [&](uint32_t buf, int k0) {
#pragma unroll
        for (int i = 0; i < 2; i++) {
            int c   = tid + i * 256;
            int row = c >> 2;
            int c4  = c & 3;
            CP16(buf + row * FFROW + c4 * 16, WB + (size_t)row * DSZ + k0 + c4 * 8);
        }
    };

    float4 va[4];
#pragma unroll
    for (int i = 0; i < 4; i++)
        va[i] = rowok[i] ? *(const float4*)(arow[i] + colf[i] * 4)
                         : make_float4(0.f, 0.f, 0.f, 0.f);
    load_B(sb + FF_BB, 0);
    CP_COMMIT();

    float acc[4][4][4];
#pragma unroll
    for (int mt = 0; mt < 4; mt++)
#pragma unroll
        for (int nt = 0; nt < 4; nt++)
#pragma unroll
            for (int e = 0; e < 4; e++) acc[mt][nt][e] = 0.f;

    const uint32_t aLaneOff = (uint32_t)(wm * 64 + (lane & 15)) * FFROW
                            + (uint32_t)(lane >> 4) * 16;
    const uint32_t bLaneOff = (uint32_t)(wn * 32 + (lane & 7) + ((lane >> 4) << 3)) * FFROW
                            + (uint32_t)((lane >> 3) & 1) * 16;

#pragma unroll 1
    for (int ch = 0; ch < 24; ch++) {
        const int nxt = ch + 1;
        if (nxt < 24) load_B(sb + FF_BB + (nxt & 1) * FF_BS, nxt * 32);
        CP_COMMIT();

#pragma unroll
        for (int i = 0; i < 4; i++) {
            uint32_t w0 = pack_fp16(__float2half_rn(va[i].x), __float2half_rn(va[i].y));
            uint32_t w1 = pack_fp16(__float2half_rn(va[i].z), __float2half_rn(va[i].w));
            *(uint2*)(sm + rown[i] * FFROW + colf[i] * 8) = make_uint2(w0, w1);
        }
        if (nxt < 24) {
#pragma unroll
            for (int i = 0; i < 4; i++)
                va[i] = rowok[i] ? *(const float4*)(arow[i] + nxt * 32 + colf[i] * 4)
                                 : make_float4(0.f, 0.f, 0.f, 0.f);
        }
        CP_WAIT1();
        __syncthreads();

        const uint32_t aB = sb + aLaneOff;
        const uint32_t bB = sb + FF_BB + (ch & 1) * FF_BS + bLaneOff;
#pragma unroll
        for (int ks = 0; ks < 2; ks++) {
            uint32_t aF[4][4];
#pragma unroll
            for (int mt = 0; mt < 4; mt++)
                LDMX4(aF[mt], aB + (uint32_t)mt * 16 * FFROW + (uint32_t)ks * 32);
            uint32_t bF[2][4];
#pragma unroll
            for (int np = 0; np < 2; np++)
                LDMX4(bF[np], bB + (uint32_t)np * 16 * FFROW + (uint32_t)ks * 32);
#pragma unroll
            for (int mt = 0; mt < 4; mt++)
#pragma unroll
                for (int nt = 0; nt < 4; nt++)
                    MMA_FP(acc[mt][nt], aF[mt],
                           bF[nt >> 1][(nt & 1) * 2], bF[nt >> 1][(nt & 1) * 2 + 1]);
        }
        __syncthreads();
    }

    float2 bv[4];
#pragma unroll
    for (int nt = 0; nt < 4; nt++)
        bv[nt] = *(const float2*)&bias[wn * 32 + nt * 8 + (lane & 3) * 2];

#pragma unroll
    for (int mt = 0; mt < 4; mt++) {
#pragma unroll
        for (int half = 0; half < 2; half++) {
            const int row  = wm * 64 + mt * 16 + (lane >> 2) + half * 8;
            const int grow = m0 + row;
            if (grow >= M) continue;
#pragma unroll
            for (int nt = 0; nt < 4; nt++) {
                const int col = wn * 32 + nt * 8 + (lane & 3) * 2;
                float f0 = fmaxf(acc[mt][nt][half * 2 + 0] + bv[nt].x, 0.f);
                float f1 = fmaxf(acc[mt][nt][half * 2 + 1] + bv[nt].y, 0.f);
                uint32_t pk = pack_fp16(__float2half_rn(f0), __float2half_rn(f1));
                if (branch == 0)
                    *(uint32_t*)&g_headH[(size_t)grow * HSZ + col] = pk;
                else
                    *(uint32_t*)&g_tailH[(size_t)grow * HSZ + col] = pk;
            }
        }
    }
}

// ---------------------------------------------------------------------------
// Kernel 2: biaffine v12 — 512 threads, warp grid 4(wm) x 4(wn), tile m32xn32.
//   acc shrinks to 32 floats/thread -> <=64 regs -> 2 CTA/SM = 32 warps/SM.
//   128 tokens x 6 r per CTA; A+tail smem resident; B via LDG.128 fragments
//   (each warp reads its n32 quarter). 4 per-wn red buffers, one end barrier,
//   coalesced combined store.
// ---------------------------------------------------------------------------
#define AROW 272
#define ATILE (128 * AROW)             // 34816
#define TTILE (128 * AROW)
#define BI_RED (ATILE + TTILE)         // 69632; 4 bufs x 6r x 128 floats
#define BI_SMEM (BI_RED + 4 * 6 * 128 * 4)   // 81920

__global__ __launch_bounds__(512, 2) void biaffine_mma(
    const int* __restrict__ head_id,
    float* __restrict__ out)
{
    extern __shared__ char sm[];
    const uint32_t sb = smem_u32(sm);
    float* red = (float*)(sm + BI_RED);

    const int t0  = blockIdx.x * 128;
    const int r0  = blockIdx.y * 6;
    const int tid = threadIdx.x;
    const int lane = tid & 31;
    const int warp = tid >> 5;       // 0..15
    const int wm   = warp & 3;       // 0..3 (32 tokens each)
    const int wn   = warp >> 2;      // 0..3 (32 k-cols each)

    // Stage A (gathered head rows) and tail, both fp16, via cp.async.
#pragma unroll
    for (int i = 0; i < 4; i++) {
        int c   = tid + i * 512;     // 0..2047
        int row = c >> 4;
        int col = c & 15;
        int t   = t0 + row;
        int hid = head_id[t];
        size_t hbase = ((size_t)(t >> 10) * APP + hid) * HSZ + col * 8;
        CP16(sb + (uint32_t)row * AROW + col * 16, g_headH + hbase);
        CP16(sb + ATILE + (uint32_t)row * AROW + col * 16,
             g_tailH + (size_t)t * HSZ + col * 8);
    }
    CP_COMMIT();
    CP_WAIT0();
    __syncthreads();

    const uint32_t aBase = sb + (uint32_t)(wm * 32 + (lane & 15)) * AROW
                         + (uint32_t)(lane >> 4) * 16;

    // tail smem read base: row = wm*32 + mt*16 + (lane>>2) + half*8, cols wn*32..
    const char* tbase = sm + ATILE
                      + ((uint32_t)(wm * 32 + (lane >> 2)) * AROW)
                      + (uint32_t)(wn * 32 + (lane & 3) * 2) * 2;

    float* rbuf = red + wn * (6 * 128);

#pragma unroll 1
    for (int rr = 0; rr < 6; rr++) {
        const int r = r0 + rr;
        // warp's n32 quarter: g in {2*wn, 2*wn+1} -> uint4 offset wn*64
        const uint4* __restrict__ bF = g_Bfrag + (size_t)r * 2048 + wn * 64 + lane;

        float acc[2][4][4];
#pragma unroll
        for (int mt = 0; mt < 2; mt++)
#pragma unroll
            for (int nb = 0; nb < 4; nb++)
#pragma unroll
                for (int e = 0; e < 4; e++) acc[mt][nb][e] = 0.f;

#pragma unroll
        for (int ks = 0; ks < 8; ks++) {
            uint32_t a0[4], a1[4];
            LDMX4(a0, aBase + ks * 32);
            LDMX4(a1, aBase + 16 * AROW + ks * 32);
            const uint4* bk = bF + ks * 256;
            uint4 bv0 = bk[0];
            uint4 bv1 = bk[32];
            MMA_FP(acc[0][0], a0, bv0.x, bv0.y);
            MMA_FP(acc[0][1], a0, bv0.z, bv0.w);
            MMA_FP(acc[0][2], a0, bv1.x, bv1.y);
            MMA_FP(acc[0][3], a0, bv1.z, bv1.w);
            MMA_FP(acc[1][0], a1, bv0.x, bv0.y);
            MMA_FP(acc[1][1], a1, bv0.z, bv0.w);
            MMA_FP(acc[1][2], a1, bv1.x, bv1.y);
            MMA_FP(acc[1][3], a1, bv1.z, bv1.w);
        }

        // partial k-dot with tail (this warp's 32 cols), quad reduce,
        // write to this r's slot in this wn's buffer (no barrier).
#pragma unroll
        for (int mt = 0; mt < 2; mt++) {
#pragma unroll
            for (int half = 0; half < 2; half++) {
                const char* trow = tbase + (uint32_t)(mt * 16 + half * 8) * AROW;
                float s = 0.f;
#pragma unroll
                for (int nb = 0; nb < 4; nb++) {
                    uint32_t tv = *(const uint32_t*)(trow + nb * 16);
                    float2 tf = __half22float2(*(const __half2*)&tv);
                    s += acc[mt][nb][half * 2 + 0] * tf.x
                       + acc[mt][nb][half * 2 + 1] * tf.y;
                }
                s += __shfl_xor_sync(0xffffffffu, s, 1);
                s += __shfl_xor_sync(0xffffffffu, s, 2);
                if ((lane & 3) == 0) {
                    int lrow = wm * 32 + mt * 16 + (lane >> 2) + half * 8;
                    rbuf[rr * 128 + lrow] = s;
                }
            }
        }
    }

    // single barrier, then coalesced combined store (24B runs per token)
    __syncthreads();
#pragma unroll
    for (int i = 0; i < 2; i++) {
        int idx = tid + i * 512;           // 0..1023, need < 768
        if (idx < 768) {
            int lrow = idx / 6;
            int rr   = idx - lrow * 6;
            int slot = rr * 128 + lrow;
            out[(size_t)(t0 + lrow) * RSZ + (r0 + rr)] =
                (red[slot] + red[768 + slot]) + (red[1536 + slot] + red[2304 + slot]);
        }
    }
}

// ---------------------------------------------------------------------------
extern "C" void kernel_launch(void* const* d_in, const int* in_sizes, int n_in,
                              void* d_out, int out_size)
{
    const float* x       = (const float*)d_in[0];
    const int*   head_id = (const int*)  d_in[1];
    const float* root    = (const float*)d_in[2];
    const float* Wh      = (const float*)d_in[3];
    const float* bh      = (const float*)d_in[4];
    const float* Wt      = (const float*)d_in[5];
    const float* bt      = (const float*)d_in[6];
    const float* Kmat    = (const float*)d_in[7];
    float*       out     = (float*)d_out;

    prep_all<<<dim3(RSZ, 5), 256>>>(Kmat, Wh, Wt);

    cudaFuncSetAttribute(ff_mma, cudaFuncAttributeMaxDynamicSharedMemorySize, FF_SMEM);
    ff_mma<<<dim3(257, 2), 256, FF_SMEM>>>(x, root, bh, bt);

    cudaFuncSetAttribute(biaffine_mma, cudaFuncAttributeMaxDynamicSharedMemorySize, BI_SMEM);
    biaffine_mma<<<dim3(NTOK / 128, RSZ / 6), 512, BI_SMEM>>>(head_id, out);
}